// round 2
// baseline (speedup 1.0000x reference)
#include <cuda_runtime.h>
#include <cuda_bf16.h>

// Grid shape is fixed for this problem instance.
#define GH 704
#define GW 704
#define GD 64

__device__ float g_sum;

__global__ void zero_kernel() { g_sum = 0.0f; }

__device__ __forceinline__ float read_grid_factor(const void* p) {
    // grid_factor may be stored as int32 (10) or float32 (10.0f).
    int bits = *(const int*)p;
    if (bits > 0 && bits < 1000000) return (float)bits;     // small int pattern
    return __int_as_float(bits);                             // float pattern
}

__global__ __launch_bounds__(256)
void dt_loss_kernel(const float* __restrict__ pc1,
                    const float* __restrict__ flow,
                    const float* __restrict__ grid,
                    const float* __restrict__ gmin,
                    const void*  __restrict__ gfac,
                    float* __restrict__ out,
                    int N, int off)
{
    int i = blockIdx.x * blockDim.x + threadIdx.x;

    float val = 0.0f;
    if (i < N) {
        const float gf = read_grid_factor(gfac);
        const float gx = __ldg(&gmin[0]);
        const float gy = __ldg(&gmin[1]);
        const float gz = __ldg(&gmin[2]);

        float px = pc1[3 * i + 0] + flow[3 * i + 0];
        float py = pc1[3 * i + 1] + flow[3 * i + 1];
        float pz = pc1[3 * i + 2] + flow[3 * i + 2];

        float sx = fminf(fmaxf((px - gx) * gf, 0.0f), (float)(GH - 1));
        float sy = fminf(fmaxf((py - gy) * gf, 0.0f), (float)(GW - 1));
        float sz = fminf(fmaxf((pz - gz) * gf, 0.0f), (float)(GD - 1));

        int x0 = (int)floorf(sx); int x1 = min(x0 + 1, GH - 1);
        int y0 = (int)floorf(sy); int y1 = min(y0 + 1, GW - 1);
        int z0 = (int)floorf(sz); int z1 = min(z0 + 1, GD - 1);

        float wx = sx - (float)x0;
        float wy = sy - (float)y0;
        float wz = sz - (float)z0;

        // idx(x,y,z) = (x*GW + y)*GD + z
        long b00 = ((long)x0 * GW + y0) * GD;
        long b01 = ((long)x0 * GW + y1) * GD;
        long b10 = ((long)x1 * GW + y0) * GD;
        long b11 = ((long)x1 * GW + y1) * GD;

        float c000 = __ldg(&grid[b00 + z0]);
        float c001 = __ldg(&grid[b00 + z1]);
        float c010 = __ldg(&grid[b01 + z0]);
        float c011 = __ldg(&grid[b01 + z1]);
        float c100 = __ldg(&grid[b10 + z0]);
        float c101 = __ldg(&grid[b10 + z1]);
        float c110 = __ldg(&grid[b11 + z0]);
        float c111 = __ldg(&grid[b11 + z1]);

        float c00 = c000 + (c001 - c000) * wz;
        float c01 = c010 + (c011 - c010) * wz;
        float c10 = c100 + (c101 - c100) * wz;
        float c11 = c110 + (c111 - c110) * wz;

        float c0 = c00 + (c01 - c00) * wy;
        float c1 = c10 + (c11 - c10) * wy;

        val = c0 + (c1 - c0) * wx;
        out[off + i] = val;
    }

    // Block reduction of val -> atomicAdd partial sums.
    __shared__ float warp_sums[8];
    int lane = threadIdx.x & 31;
    int wid  = threadIdx.x >> 5;

    #pragma unroll
    for (int d = 16; d > 0; d >>= 1)
        val += __shfl_down_sync(0xFFFFFFFFu, val, d);

    if (lane == 0) warp_sums[wid] = val;
    __syncthreads();

    if (wid == 0) {
        float s = (lane < 8) ? warp_sums[lane] : 0.0f;
        #pragma unroll
        for (int d = 4; d > 0; d >>= 1)
            s += __shfl_down_sync(0xFFFFFFFFu, s, d);
        if (lane == 0) atomicAdd(&g_sum, s);
    }
}

__global__ void finalize_kernel(float* __restrict__ out, int N) {
    out[0] = g_sum / (float)N;
}

extern "C" void kernel_launch(void* const* d_in, const int* in_sizes, int n_in,
                              void* d_out, int out_size)
{
    const float* pc1  = (const float*)d_in[0];
    const float* flow = (const float*)d_in[1];
    const float* grid = (const float*)d_in[2];
    const float* gmin = (const float*)d_in[3];
    const void*  gfac = d_in[4];
    float* out = (float*)d_out;

    int N = in_sizes[0] / 3;
    int off = out_size - N;   // 1 if [mean, dist...], 0 if just [dist...]
    if (off < 0) off = 0;

    zero_kernel<<<1, 1>>>();

    int threads = 256;
    int blocks = (N + threads - 1) / threads;
    dt_loss_kernel<<<blocks, threads>>>(pc1, flow, grid, gmin, gfac, out, N, off);

    if (off > 0) {
        finalize_kernel<<<1, 1>>>(out, N);
    }
}